// round 1
// baseline (speedup 1.0000x reference)
#include <cuda_runtime.h>

// Problem constants (fixed shapes for this problem instance)
constexpr int Tn = 1000;   // timesteps
constexpr int Dd = 64;     // input dim
constexpr int Nn = 128;    // neurons
constexpr int Bb = 1000;   // batch rows (= T in reference)
constexpr int ROWS_PER_CTA = 8;   // 8 warps per CTA, one row per warp

// Scratch: per-step input currents inp_cur[t][n] = input_signal[t,:] @ input_weights[:,n]
__device__ float g_inp_cur[Tn * Nn];

// ---------------------------------------------------------------------------
// Kernel A: tiny GEMM (1000x64 @ 64x128) -> g_inp_cur. Negligible cost.
// ---------------------------------------------------------------------------
__global__ void inp_cur_kernel(const float* __restrict__ sig,
                               const float* __restrict__ w_in) {
    int t = blockIdx.x;
    int n = threadIdx.x;
    float acc = 0.f;
#pragma unroll
    for (int d = 0; d < Dd; ++d)
        acc += sig[t * Dd + d] * w_in[d * Nn + n];
    g_inp_cur[t * Nn + n] = acc;
}

// ---------------------------------------------------------------------------
// Kernel B: warp-per-row SNN simulation.
//   - Lane l owns neurons 4l..4l+3 (float4 state in registers).
//   - W_rec (128x128 fp32 = 64KB) lives in dynamic SMEM, shared by 8 warps.
//   - rec_t = trace_t @ W maintained incrementally:
//       rec = 0.95*rec + sum_{k in spikes} W[k][:]
//     using ballot masks + uniform bit-scan loop (no divergence: mask is
//     warp-uniform).
// ---------------------------------------------------------------------------
__global__ __launch_bounds__(ROWS_PER_CTA * 32, 1)
void sim_kernel(const float* __restrict__ Wrec, float* __restrict__ out) {
    extern __shared__ float sW[];  // Nn*Nn floats = 64KB

    int tid = threadIdx.x;
    // Cooperative vectorized load of W_rec into SMEM
    {
        const float4* src = reinterpret_cast<const float4*>(Wrec);
        float4* dst = reinterpret_cast<float4*>(sW);
        for (int i = tid; i < (Nn * Nn) / 4; i += blockDim.x) dst[i] = src[i];
    }
    __syncthreads();

    const int warp = tid >> 5;
    const int lane = tid & 31;
    const int row = blockIdx.x * ROWS_PER_CTA + warp;   // 0..999 (exact: 125*8)

    float* __restrict__ out_spk = out + (size_t)row * Tn * Nn;
    float* __restrict__ out_mem = out + (size_t)Bb * Tn * Nn + (size_t)row * Tn * Nn;
    float* __restrict__ out_trc = out + (size_t)2 * Bb * Tn * Nn + (size_t)row * Nn;

    float mem[4]  = {0.f, 0.f, 0.f, 0.f};
    float syn[4]  = {0.f, 0.f, 0.f, 0.f};
    float refr[4] = {0.f, 0.f, 0.f, 0.f};
    float rec[4]  = {0.f, 0.f, 0.f, 0.f};   // = trace_{t-1} @ W (incremental)
    float trc[4]  = {0.f, 0.f, 0.f, 0.f};

    const float4* __restrict__ xin = reinterpret_cast<const float4*>(g_inp_cur);
    // Prefetch t=0 input current (32 float4 per row of 128 floats)
    float4 x = xin[lane];

    for (int t = 0; t < Tn; ++t) {
        // Prefetch next step's input current (L2/L1 resident, shared by all rows)
        int tnext = (t + 1 < Tn) ? (t + 1) : (Tn - 1);
        float4 xnext = xin[tnext * (Nn / 4) + lane];

        float s[4];
        const float xv[4] = {x.x, x.y, x.z, x.w};
#pragma unroll
        for (int j = 0; j < 4; ++j) {
            // syn = syn*(1 - 1/5) + x + rec
            syn[j] = syn[j] * 0.8f + xv[j] + rec[j];
            // mem = mem*(1 - 1/10) + syn/10
            mem[j] = mem[j] * 0.9f + syn[j] / 10.0f;
            // refractory masking (pre-decrement), then decrement
            if (refr[j] > 0.f) mem[j] = 0.f;
            refr[j] = fmaxf(refr[j] - 1.0f, 0.0f);
            // spike, reset, refractory extend, trace update
            s[j] = (mem[j] > 1.0f) ? 1.0f : 0.0f;
            mem[j] = mem[j] * (1.0f - s[j]);
            refr[j] += s[j] * 2.0f;
            trc[j] = trc[j] * 0.95f + s[j];
        }

        // Coalesced 512B stores per warp for spikes and membrane history
        reinterpret_cast<float4*>(out_spk + (size_t)t * Nn)[lane] =
            make_float4(s[0], s[1], s[2], s[3]);
        reinterpret_cast<float4*>(out_mem + (size_t)t * Nn)[lane] =
            make_float4(mem[0], mem[1], mem[2], mem[3]);

        // Incremental recurrent update: rec = 0.95*rec + sum_{spiking k} W[k][:]
        float acc0 = 0.f, acc1 = 0.f, acc2 = 0.f, acc3 = 0.f;
#pragma unroll
        for (int j = 0; j < 4; ++j) {
            unsigned m = __ballot_sync(0xFFFFFFFFu, s[j] > 0.f);
            while (m) {               // warp-uniform loop (m identical on all lanes)
                int l = __ffs(m) - 1;
                m &= m - 1;
                int k = (l << 2) + j; // spiking neuron index
                float4 w = reinterpret_cast<const float4*>(sW + k * Nn)[lane];
                acc0 += w.x; acc1 += w.y; acc2 += w.z; acc3 += w.w;
            }
        }
        rec[0] = rec[0] * 0.95f + acc0;
        rec[1] = rec[1] * 0.95f + acc1;
        rec[2] = rec[2] * 0.95f + acc2;
        rec[3] = rec[3] * 0.95f + acc3;

        x = xnext;
    }

    // Final trace output (B, N)
    reinterpret_cast<float4*>(out_trc)[lane] =
        make_float4(trc[0], trc[1], trc[2], trc[3]);
}

// ---------------------------------------------------------------------------
// Harness entry
// ---------------------------------------------------------------------------
extern "C" void kernel_launch(void* const* d_in, const int* in_sizes, int n_in,
                              void* d_out, int out_size) {
    const float* sig   = (const float*)d_in[0];  // (1000, 64)
    const float* w_in  = (const float*)d_in[1];  // (64, 128)
    const float* w_rec = (const float*)d_in[2];  // (128, 128)
    float* out = (float*)d_out;

    static bool attr_set = false;
    // Attribute set is idempotent and not a stream op; safe under capture.
    cudaFuncSetAttribute(sim_kernel, cudaFuncAttributeMaxDynamicSharedMemorySize,
                         Nn * Nn * (int)sizeof(float));
    (void)attr_set; (void)in_sizes; (void)n_in; (void)out_size;

    inp_cur_kernel<<<Tn, Nn>>>(sig, w_in);
    sim_kernel<<<Bb / ROWS_PER_CTA, ROWS_PER_CTA * 32,
                 Nn * Nn * (int)sizeof(float)>>>(w_rec, out);
}

// round 2
// speedup vs baseline: 1.0182x; 1.0182x over previous
#include <cuda_runtime.h>

// Problem constants (fixed shapes for this problem instance)
constexpr int Tn = 1000;   // timesteps
constexpr int Dd = 64;     // input dim
constexpr int Nn = 128;    // neurons
constexpr int Bb = 1000;   // batch rows
constexpr int ROWS_PER_CTA = 4;           // 8 warps per CTA, 2 warps per row
constexpr int THREADS = ROWS_PER_CTA * 2 * 32;  // 256

// Scratch: per-step input currents inp_cur[t][n] = input_signal[t,:] @ input_weights[:,n]
__device__ float g_inp_cur[Tn * Nn];

// ---------------------------------------------------------------------------
// Kernel A: tiny GEMM (1000x64 @ 64x128) -> g_inp_cur. Negligible cost.
// ---------------------------------------------------------------------------
__global__ void inp_cur_kernel(const float* __restrict__ sig,
                               const float* __restrict__ w_in) {
    int t = blockIdx.x;
    int n = threadIdx.x;
    float acc = 0.f;
#pragma unroll
    for (int d = 0; d < Dd; ++d)
        acc += sig[t * Dd + d] * w_in[d * Nn + n];
    g_inp_cur[t * Nn + n] = acc;
}

// ---------------------------------------------------------------------------
// Kernel B: 2-warps-per-row SNN simulation.
//   - Warp pair (2r, 2r+1) owns row r; warp half h owns neurons [64h, 64h+64).
//   - Lane l owns neurons 64h + 2l, 64h + 2l + 1 (float2 state in registers).
//   - W_rec (128x128 fp32 = 64KB) in dynamic SMEM, shared by all 8 warps.
//   - rec_t = trace_t @ W maintained incrementally via sparse spike masks:
//       rec = 0.95*rec + sum_{k in spikes} W[k][my 64 cols]
//   - Spike masks exchanged between the two warps of a row through static
//     SMEM, double-buffered by (t&1), one named barrier (per row pair) per step.
// ---------------------------------------------------------------------------
__global__ __launch_bounds__(THREADS, 2)
void sim_kernel(const float* __restrict__ Wrec, float* __restrict__ out) {
    extern __shared__ float sW[];                 // Nn*Nn floats = 64KB
    __shared__ unsigned smask[2][8][2];           // [buf][warp][word]

    const int tid = threadIdx.x;
    // Cooperative vectorized load of W_rec into SMEM
    {
        const float4* src = reinterpret_cast<const float4*>(Wrec);
        float4* dst = reinterpret_cast<float4*>(sW);
        for (int i = tid; i < (Nn * Nn) / 4; i += THREADS) dst[i] = src[i];
    }
    __syncthreads();

    const int warp = tid >> 5;
    const int lane = tid & 31;
    const int rloc = warp >> 1;        // row within CTA (0..3)
    const int half = warp & 1;         // which 64-neuron half this warp owns
    const int row = blockIdx.x * ROWS_PER_CTA + rloc;   // 0..999
    const int colv = half * 32 + lane; // float2 column index within the 64-f2 row
    const int barid = rloc + 1;        // named barrier per row pair
    const int peer = warp ^ 1;

    float2* __restrict__ out_spk =
        reinterpret_cast<float2*>(out + (size_t)row * Tn * Nn);
    float2* __restrict__ out_mem =
        reinterpret_cast<float2*>(out + (size_t)Bb * Tn * Nn + (size_t)row * Tn * Nn);
    float2* __restrict__ out_trc =
        reinterpret_cast<float2*>(out + (size_t)2 * Bb * Tn * Nn + (size_t)row * Nn);

    const float2* __restrict__ sW2 = reinterpret_cast<const float2*>(sW);

    float2 mem  = {0.f, 0.f};
    float2 syn  = {0.f, 0.f};
    float2 refr = {0.f, 0.f};
    float2 rec  = {0.f, 0.f};   // = trace_{t-1} @ W (incremental), my 2 cols
    float2 trc  = {0.f, 0.f};

    const float2* __restrict__ xin2 = reinterpret_cast<const float2*>(g_inp_cur);
    float2 x = xin2[colv];      // t = 0 input current (my 2 cols)

    for (int t = 0; t < Tn; ++t) {
        // Prefetch next step's input current (L1/L2-resident, shared by all rows)
        const int tnext = (t + 1 < Tn) ? (t + 1) : (Tn - 1);
        const float2 xnext = xin2[tnext * (Nn / 2) + colv];

        // ---- Update my 2 neurons ----
        syn.x = syn.x * 0.8f + x.x + rec.x;
        syn.y = syn.y * 0.8f + x.y + rec.y;
        mem.x = mem.x * 0.9f + syn.x * 0.1f;
        mem.y = mem.y * 0.9f + syn.y * 0.1f;
        mem.x = (refr.x > 0.f) ? 0.f : mem.x;
        mem.y = (refr.y > 0.f) ? 0.f : mem.y;
        refr.x = fmaxf(refr.x - 1.f, 0.f);
        refr.y = fmaxf(refr.y - 1.f, 0.f);
        const bool k0 = mem.x > 1.0f;
        const bool k1 = mem.y > 1.0f;
        const float s0 = k0 ? 1.f : 0.f;
        const float s1 = k1 ? 1.f : 0.f;
        mem.x = k0 ? 0.f : mem.x;
        mem.y = k1 ? 0.f : mem.y;
        refr.x += s0 * 2.f;
        refr.y += s1 * 2.f;
        trc.x = trc.x * 0.95f + s0;
        trc.y = trc.y * 0.95f + s1;

        // ---- Exchange spike masks with peer warp ----
        // bit l of word j  <->  neuron 64*half + 2l + j
        const unsigned m0 = __ballot_sync(0xFFFFFFFFu, k0);
        const unsigned m1 = __ballot_sync(0xFFFFFFFFu, k1);
        const int buf = t & 1;
        if (lane == 0) {
            smask[buf][warp][0] = m0;
            smask[buf][warp][1] = m1;
        }
        asm volatile("bar.sync %0, 64;" :: "r"(barid) : "memory");
        const unsigned p0 = smask[buf][peer][0];
        const unsigned p1 = smask[buf][peer][1];

        // ---- Coalesced 256B stores per warp (spikes, membrane) ----
        out_spk[t * (Nn / 2) + colv] = make_float2(s0, s1);
        out_mem[t * (Nn / 2) + colv] = mem;

        // ---- Incremental recurrent update over 4 spike-mask words ----
        float ax = 0.f, ay = 0.f;
        const int bo = half * 64;        // my warp's neuron base
        const int bp = bo ^ 64;          // peer warp's neuron base
        unsigned m;
        m = m0;
        while (m) { int l = __ffs(m) - 1; m &= m - 1;
            const float2 w = sW2[(bo + 2 * l)     * (Nn / 2) + colv]; ax += w.x; ay += w.y; }
        m = m1;
        while (m) { int l = __ffs(m) - 1; m &= m - 1;
            const float2 w = sW2[(bo + 2 * l + 1) * (Nn / 2) + colv]; ax += w.x; ay += w.y; }
        m = p0;
        while (m) { int l = __ffs(m) - 1; m &= m - 1;
            const float2 w = sW2[(bp + 2 * l)     * (Nn / 2) + colv]; ax += w.x; ay += w.y; }
        m = p1;
        while (m) { int l = __ffs(m) - 1; m &= m - 1;
            const float2 w = sW2[(bp + 2 * l + 1) * (Nn / 2) + colv]; ax += w.x; ay += w.y; }

        rec.x = rec.x * 0.95f + ax;
        rec.y = rec.y * 0.95f + ay;

        x = xnext;
    }

    // Final trace output (B, N)
    out_trc[colv] = trc;
}

// ---------------------------------------------------------------------------
// Harness entry
// ---------------------------------------------------------------------------
extern "C" void kernel_launch(void* const* d_in, const int* in_sizes, int n_in,
                              void* d_out, int out_size) {
    const float* sig   = (const float*)d_in[0];  // (1000, 64)
    const float* w_in  = (const float*)d_in[1];  // (64, 128)
    const float* w_rec = (const float*)d_in[2];  // (128, 128)
    float* out = (float*)d_out;
    (void)in_sizes; (void)n_in; (void)out_size;

    cudaFuncSetAttribute(sim_kernel, cudaFuncAttributeMaxDynamicSharedMemorySize,
                         Nn * Nn * (int)sizeof(float));

    inp_cur_kernel<<<Tn, Nn>>>(sig, w_in);
    sim_kernel<<<Bb / ROWS_PER_CTA, THREADS,
                 Nn * Nn * (int)sizeof(float)>>>(w_rec, out);
}